// round 1
// baseline (speedup 1.0000x reference)
#include <cuda_runtime.h>
#include <cstdint>

// Problem constants
#define NPTS   32768      // B*N = 8*4096
#define KNBR   32
#define CIN    128
#define HDIM   64
#define PDIM   32
#define PPC    8          // points per CTA
#define NTHR   256

struct Smem {
    float W[128 * 128];     // [theta|z] weights, bank-permuted layout (see sidx)
    float X[64 * 132];      // 2 points x 32 rows x 128 cols, row stride 132 (pad)
    float CF[256];          // center features, 2 points
    float FI[128];          // feat_i (relu(cf@phi+b)), 2 x 64
    float TB[64];           // theta_b
    float ZB[64];           // z_b
    float PB[64];           // phi_b
    float RF[64];           // r_f dot, 2 x 32
    float DNK[64];          // neighbor part of psi dot, 2 x 32
    float MK[64];           // SPIL mask, 2 x 32
    float SI[2];            // center part of psi dot
    float Wk[64];           // softmax weights, 2 x 32
    float SumW[2];          // sum of Wk per point
    float Part[2 * 8 * 64]; // per-warp z partials
    float NX[192];          // neighbor xyz, 2 x 32 x 3
    float CX[8];            // center xyz, 2 x 4 (padded)
};

__device__ __forceinline__ unsigned long long fma2(unsigned long long a,
                                                   unsigned long long b,
                                                   unsigned long long c) {
    unsigned long long d;
    asm("fma.rn.f32x2 %0, %1, %2, %3;" : "=l"(d) : "l"(a), "l"(b), "l"(c));
    return d;
}
__device__ __forceinline__ unsigned long long pack2(float x) {
    unsigned long long d;
    asm("mov.b64 %0, {%1, %1};" : "=l"(d) : "f"(x));
    return d;
}
__device__ __forceinline__ float2 unpack2(unsigned long long v) {
    float2 r;
    asm("mov.b64 {%0, %1}, %2;" : "=f"(r.x), "=f"(r.y) : "l"(v));
    return r;
}

__global__ __launch_bounds__(NTHR, 2)
void spil_kernel(const float* __restrict__ cxyz,  const float* __restrict__ cfeat,
                 const float* __restrict__ nxyz,  const float* __restrict__ nfeat,
                 const float* __restrict__ phi_w, const float* __restrict__ phi_b,
                 const float* __restrict__ theta_w, const float* __restrict__ theta_b,
                 const float* __restrict__ m1_w,  const float* __restrict__ m1_b,
                 const float* __restrict__ m2_w,  const float* __restrict__ m2_b,
                 const float* __restrict__ psi_w, const float* __restrict__ psi_b,
                 const float* __restrict__ z_w,   const float* __restrict__ z_b,
                 float* __restrict__ out)
{
    extern __shared__ char smem_raw[];
    Smem* s = reinterpret_cast<Smem*>(smem_raw);

    const int t = threadIdx.x;
    const int w = t >> 5;
    const int l = t & 31;
    const int rloc = l >> 3;   // 0..3: row within warp's row group
    const int cg = l & 7;      // 0..7: 16-column group (cg<4: theta, cg>=4: z)
    const int row = w * 4 + rloc;  // 0..31: neighbor index k

    const float psib = psi_b[0];
    const int p0base = blockIdx.x * PPC;

    // ---- Stage combined weight matrix [theta_w | z_w] with bank permutation.
    // Logical col o -> storage sidx = j*32 + cg*4 + i  (o = cg*16 + j*4 + i)
    // so one LDS.128 across the 8 cg lanes covers one contiguous 128B phase.
    for (int idx = t; idx < 128 * 128; idx += NTHR) {
        int c = idx >> 7, o = idx & 127;
        float v = (o < 64) ? theta_w[c * 64 + o] : z_w[c * 64 + (o - 64)];
        int sidx = ((o >> 2) & 3) * 32 + ((o >> 4) << 2) + (o & 3);
        s->W[c * 128 + sidx] = v;
    }
    if (t < 64) {
        s->TB[t] = theta_b[t];
        s->ZB[t] = z_b[t];
        s->PB[t] = phi_b[t];
    }
    __syncthreads();

    const ulonglong2* W2 = reinterpret_cast<const ulonglong2*>(s->W);

    for (int pp = 0; pp < PPC; pp += 2) {
        const int p0 = p0base + pp;  // process points p0, p0+1 together

        // ---- Stage inputs for the two points ----
        {
            const float4* src4 = reinterpret_cast<const float4*>(nfeat + (size_t)p0 * KNBR * CIN);
            float4* dst4 = reinterpret_cast<float4*>(s->X);
            #pragma unroll
            for (int i = t; i < 2048; i += NTHR) {
                float4 v = src4[i];
                int r = i >> 5;       // 32 float4 per 128-float row
                int c4 = i & 31;
                dst4[r * 33 + c4] = v; // row stride 132 floats = 33 float4
            }
            s->CF[t] = cfeat[(size_t)p0 * CIN + t];
            if (t < 192) s->NX[t] = nxyz[(size_t)p0 * KNBR * 3 + t];
            if (t < 6)   s->CX[(t / 3) * 4 + (t % 3)] = cxyz[(size_t)p0 * 3 + t];
        }
        __syncthreads();

        // ---- Side computations on dedicated warps ----
        if (t < 128) {
            // feat_i = relu(center_features @ phi_w + phi_b), 2 points x 64
            int p = t >> 6, h = t & 63;
            const float* cf = s->CF + p * 128;
            float a0 = 0.f, a1 = 0.f, a2 = 0.f, a3 = 0.f;
            #pragma unroll 8
            for (int c = 0; c < 128; c += 4) {
                a0 += cf[c]     * phi_w[c * 64 + h];
                a1 += cf[c + 1] * phi_w[(c + 1) * 64 + h];
                a2 += cf[c + 2] * phi_w[(c + 2) * 64 + h];
                a3 += cf[c + 3] * phi_w[(c + 3) * 64 + h];
            }
            s->FI[t] = fmaxf(a0 + a1 + a2 + a3 + s->PB[h], 0.f);
        } else if (t < 192) {
            // per-(point,k): neighbor half of psi dot + SPIL mask
            int u = t - 128;
            int p = u >> 5;
            const float* nx = s->NX + u * 3;
            float x0 = nx[0], x1 = nx[1], x2 = nx[2];
            float dotv = 0.f;
            #pragma unroll
            for (int q = 0; q < PDIM; ++q) {
                float pj = fmaxf(x0 * m2_w[q] + x1 * m2_w[32 + q] + x2 * m2_w[64 + q] + m2_b[q], 0.f);
                dotv += pj * psi_w[32 + q];
            }
            s->DNK[u] = dotv;
            float c0 = s->CX[p * 4 + 0], c1 = s->CX[p * 4 + 1], c2 = s->CX[p * 4 + 2];
            float dx = c0 - x0, dy = c1 - x1, dz = c2 - x2;
            float dist = sqrtf(dx * dx + dy * dy + dz * dz);
            s->MK[u] = ((c2 == x2) && (dist > 0.04f)) ? 1.f : 0.f;
        } else if (t < 194) {
            // center half of psi dot
            int p = t - 192;
            float c0 = s->CX[p * 4 + 0], c1 = s->CX[p * 4 + 1], c2 = s->CX[p * 4 + 2];
            float si = 0.f;
            #pragma unroll
            for (int q = 0; q < PDIM; ++q) {
                float pi = fmaxf(c0 * m1_w[q] + c1 * m1_w[32 + q] + c2 * m1_w[64 + q] + m1_b[q], 0.f);
                si += pi * psi_w[q];
            }
            s->SI[p] = si;
        }
        __syncthreads();

        // ---- Main GEMM: 64 rows (2 points x 32 nbrs) x 128 cols, K=128 ----
        // Thread: rows (row, row+32), 16 cols (8 packed f32x2 accumulators each).
        const float* xa = s->X + row * 132;
        const float* xb = s->X + (row + 32) * 132;
        unsigned long long accA[8], accB[8];
        #pragma unroll
        for (int i = 0; i < 8; ++i) { accA[i] = 0ull; accB[i] = 0ull; }

        #pragma unroll 4
        for (int c = 0; c < 128; ++c) {
            unsigned long long xa2 = pack2(xa[c]);
            unsigned long long xb2 = pack2(xb[c]);
            const ulonglong2* wr = W2 + c * 32 + cg;
            #pragma unroll
            for (int j = 0; j < 4; ++j) {
                ulonglong2 wv = wr[j * 8];
                accA[2 * j]     = fma2(xa2, wv.x, accA[2 * j]);
                accA[2 * j + 1] = fma2(xa2, wv.y, accA[2 * j + 1]);
                accB[2 * j]     = fma2(xb2, wv.x, accB[2 * j]);
                accB[2 * j + 1] = fma2(xb2, wv.y, accB[2 * j + 1]);
            }
        }

        // ---- r_f = dot(relu(theta_out + tb), feat_i) per (point,k) ----
        #pragma unroll
        for (int p = 0; p < 2; ++p) {
            unsigned long long* acc = p ? accB : accA;
            float part = 0.f;
            if (cg < 4) {
                #pragma unroll
                for (int j = 0; j < 4; ++j) {
                    float2 v0 = unpack2(acc[2 * j]);
                    float2 v1 = unpack2(acc[2 * j + 1]);
                    int o = cg * 16 + j * 4;
                    part += fmaxf(v0.x + s->TB[o],     0.f) * s->FI[p * 64 + o];
                    part += fmaxf(v0.y + s->TB[o + 1], 0.f) * s->FI[p * 64 + o + 1];
                    part += fmaxf(v1.x + s->TB[o + 2], 0.f) * s->FI[p * 64 + o + 2];
                    part += fmaxf(v1.y + s->TB[o + 3], 0.f) * s->FI[p * 64 + o + 3];
                }
            }
            part += __shfl_xor_sync(0xFFFFFFFFu, part, 1);
            part += __shfl_xor_sync(0xFFFFFFFFu, part, 2);
            if (cg == 0) s->RF[p * 32 + row] = part;
        }
        __syncthreads();

        // ---- masked, r_l-weighted softmax over K (warp 0 -> p0, warp 1 -> p1) ----
        if (w < 2) {
            int p = w, k = l;
            float rf = s->RF[p * 32 + k] * 0.125f;  // / sqrt(64)
            float m = rf;
            #pragma unroll
            for (int off = 16; off; off >>= 1)
                m = fmaxf(m, __shfl_xor_sync(0xFFFFFFFFu, m, off));
            float rl = fmaxf(s->SI[p] + s->DNK[p * 32 + k] + psib, 0.f)
                     * (1.f - s->MK[p * 32 + k]);
            float num = rl * expf(rf - m);
            float den = num;
            #pragma unroll
            for (int off = 16; off; off >>= 1)
                den += __shfl_xor_sync(0xFFFFFFFFu, den, off);
            den += 1e-8f;
            float Wk = num / den;
            s->Wk[p * 32 + k] = Wk;
            float sw = Wk;
            #pragma unroll
            for (int off = 16; off; off >>= 1)
                sw += __shfl_xor_sync(0xFFFFFFFFu, sw, off);
            if (k == 0) s->SumW[p] = sw;
        }
        __syncthreads();

        // ---- weighted reduction of z half over k ----
        #pragma unroll
        for (int p = 0; p < 2; ++p) {
            unsigned long long* acc = p ? accB : accA;
            float Wk = s->Wk[p * 32 + row];
            float v[16];
            #pragma unroll
            for (int j = 0; j < 4; ++j) {
                float2 v0 = unpack2(acc[2 * j]);
                float2 v1 = unpack2(acc[2 * j + 1]);
                v[j * 4 + 0] = v0.x * Wk;
                v[j * 4 + 1] = v0.y * Wk;
                v[j * 4 + 2] = v1.x * Wk;
                v[j * 4 + 3] = v1.y * Wk;
            }
            #pragma unroll
            for (int i = 0; i < 16; ++i) {
                v[i] += __shfl_xor_sync(0xFFFFFFFFu, v[i], 8);
                v[i] += __shfl_xor_sync(0xFFFFFFFFu, v[i], 16);
            }
            if (cg >= 4 && rloc == 0) {
                float* dst = s->Part + (p * 8 + w) * 64 + (cg - 4) * 16;
                #pragma unroll
                for (int i = 0; i < 16; ++i) dst[i] = v[i];
            }
        }
        __syncthreads();

        // ---- combine warp partials + z_b * sum(W), store ----
        if (t < 128) {
            int p = t >> 6, h = t & 63;
            float o = s->ZB[h] * s->SumW[p];
            #pragma unroll
            for (int w8 = 0; w8 < 8; ++w8)
                o += s->Part[(p * 8 + w8) * 64 + h];
            out[(size_t)(p0 + p) * HDIM + h] = o;
        }
        __syncthreads();
    }
}

extern "C" void kernel_launch(void* const* d_in, const int* in_sizes, int n_in,
                              void* d_out, int out_size) {
    const float* cxyz    = (const float*)d_in[0];
    const float* cfeat   = (const float*)d_in[1];
    const float* nxyz    = (const float*)d_in[2];
    const float* nfeat   = (const float*)d_in[3];
    const float* phi_w   = (const float*)d_in[4];
    const float* phi_b   = (const float*)d_in[5];
    const float* theta_w = (const float*)d_in[6];
    const float* theta_b = (const float*)d_in[7];
    const float* m1_w    = (const float*)d_in[8];
    const float* m1_b    = (const float*)d_in[9];
    const float* m2_w    = (const float*)d_in[10];
    const float* m2_b    = (const float*)d_in[11];
    const float* psi_w   = (const float*)d_in[12];
    const float* psi_b   = (const float*)d_in[13];
    const float* z_w     = (const float*)d_in[14];
    const float* z_b     = (const float*)d_in[15];
    float* out = (float*)d_out;

    cudaFuncSetAttribute(spil_kernel, cudaFuncAttributeMaxDynamicSharedMemorySize,
                         (int)sizeof(Smem));
    spil_kernel<<<NPTS / PPC, NTHR, sizeof(Smem)>>>(
        cxyz, cfeat, nxyz, nfeat, phi_w, phi_b, theta_w, theta_b,
        m1_w, m1_b, m2_w, m2_b, psi_w, psi_b, z_w, z_b, out);
}

// round 6
// speedup vs baseline: 1.0022x; 1.0022x over previous
#include <cuda_runtime.h>
#include <cstdint>

// Problem constants
#define NPTS   32768      // B*N = 8*4096
#define KNBR   32
#define CIN    128
#define HDIM   64
#define PDIM   32
#define PPC    8          // points per CTA
#define NTHR   256

struct Smem {
    float W[128 * 128];     // [theta|z] weights, bank-permuted layout (see sidx)
    float X[64 * 132];      // 2 points x 32 rows x 128 cols, row stride 132 (pad)
    float CF[256];          // center features, 2 points
    float FI[128];          // feat_i (relu(cf@phi+b)), 2 x 64
    float TB[64];           // theta_b
    float ZB[64];           // z_b
    float PB[64];           // phi_b
    float RF[64];           // r_f dot, 2 x 32
    float DNK[64];          // neighbor part of psi dot, 2 x 32
    float MK[64];           // SPIL mask, 2 x 32
    float SI[2];            // center part of psi dot
    float Wk[64];           // softmax weights, 2 x 32
    float SumW[2];          // sum of Wk per point
    float Part[2 * 8 * 64]; // per-warp z partials
    float NX[192];          // neighbor xyz, 2 x 32 x 3
    float CX[8];            // center xyz, 2 x 4 (padded)
};

__device__ __forceinline__ unsigned long long fma2(unsigned long long a,
                                                   unsigned long long b,
                                                   unsigned long long c) {
    unsigned long long d;
    asm("fma.rn.f32x2 %0, %1, %2, %3;" : "=l"(d) : "l"(a), "l"(b), "l"(c));
    return d;
}
__device__ __forceinline__ unsigned long long pack2(float x) {
    unsigned long long d;
    asm("mov.b64 %0, {%1, %1};" : "=l"(d) : "f"(x));
    return d;
}
__device__ __forceinline__ float2 unpack2(unsigned long long v) {
    float2 r;
    asm("mov.b64 {%0, %1}, %2;" : "=f"(r.x), "=f"(r.y) : "l"(v));
    return r;
}

__global__ __launch_bounds__(NTHR, 2)
void spil_kernel(const float* __restrict__ cxyz,  const float* __restrict__ cfeat,
                 const float* __restrict__ nxyz,  const float* __restrict__ nfeat,
                 const float* __restrict__ phi_w, const float* __restrict__ phi_b,
                 const float* __restrict__ theta_w, const float* __restrict__ theta_b,
                 const float* __restrict__ m1_w,  const float* __restrict__ m1_b,
                 const float* __restrict__ m2_w,  const float* __restrict__ m2_b,
                 const float* __restrict__ psi_w, const float* __restrict__ psi_b,
                 const float* __restrict__ z_w,   const float* __restrict__ z_b,
                 float* __restrict__ out)
{
    extern __shared__ char smem_raw[];
    Smem* s = reinterpret_cast<Smem*>(smem_raw);

    const int t = threadIdx.x;
    const int w = t >> 5;
    const int l = t & 31;
    const int rloc = l >> 3;   // 0..3: row within warp's row group
    const int cg = l & 7;      // 0..7: 16-column group (cg<4: theta, cg>=4: z)
    const int row = w * 4 + rloc;  // 0..31: neighbor index k

    const float psib = psi_b[0];
    const int p0base = blockIdx.x * PPC;

    // ---- Stage combined weight matrix [theta_w | z_w] with bank permutation.
    // Logical col o -> storage sidx = j*32 + cg*4 + i  (o = cg*16 + j*4 + i)
    // so one LDS.128 across the 8 cg lanes covers one contiguous 128B phase.
    for (int idx = t; idx < 128 * 128; idx += NTHR) {
        int c = idx >> 7, o = idx & 127;
        float v = (o < 64) ? theta_w[c * 64 + o] : z_w[c * 64 + (o - 64)];
        int sidx = ((o >> 2) & 3) * 32 + ((o >> 4) << 2) + (o & 3);
        s->W[c * 128 + sidx] = v;
    }
    if (t < 64) {
        s->TB[t] = theta_b[t];
        s->ZB[t] = z_b[t];
        s->PB[t] = phi_b[t];
    }
    __syncthreads();

    const ulonglong2* W2 = reinterpret_cast<const ulonglong2*>(s->W);

    for (int pp = 0; pp < PPC; pp += 2) {
        const int p0 = p0base + pp;  // process points p0, p0+1 together

        // ---- Stage inputs for the two points ----
        {
            const float4* src4 = reinterpret_cast<const float4*>(nfeat + (size_t)p0 * KNBR * CIN);
            float4* dst4 = reinterpret_cast<float4*>(s->X);
            #pragma unroll
            for (int i = t; i < 2048; i += NTHR) {
                float4 v = src4[i];
                int r = i >> 5;       // 32 float4 per 128-float row
                int c4 = i & 31;
                dst4[r * 33 + c4] = v; // row stride 132 floats = 33 float4
            }
            s->CF[t] = cfeat[(size_t)p0 * CIN + t];
            if (t < 192) s->NX[t] = nxyz[(size_t)p0 * KNBR * 3 + t];
            if (t < 6)   s->CX[(t / 3) * 4 + (t % 3)] = cxyz[(size_t)p0 * 3 + t];
        }
        __syncthreads();

        // ---- Side computations on dedicated warps ----
        if (t < 128) {
            // feat_i = relu(center_features @ phi_w + phi_b), 2 points x 64
            int p = t >> 6, h = t & 63;
            const float* cf = s->CF + p * 128;
            float a0 = 0.f, a1 = 0.f, a2 = 0.f, a3 = 0.f;
            #pragma unroll 8
            for (int c = 0; c < 128; c += 4) {
                a0 += cf[c]     * phi_w[c * 64 + h];
                a1 += cf[c + 1] * phi_w[(c + 1) * 64 + h];
                a2 += cf[c + 2] * phi_w[(c + 2) * 64 + h];
                a3 += cf[c + 3] * phi_w[(c + 3) * 64 + h];
            }
            s->FI[t] = fmaxf(a0 + a1 + a2 + a3 + s->PB[h], 0.f);
        } else if (t < 192) {
            // per-(point,k): neighbor half of psi dot + SPIL mask
            int u = t - 128;
            int p = u >> 5;
            const float* nx = s->NX + u * 3;
            float x0 = nx[0], x1 = nx[1], x2 = nx[2];
            float dotv = 0.f;
            #pragma unroll
            for (int q = 0; q < PDIM; ++q) {
                float pj = fmaxf(x0 * m2_w[q] + x1 * m2_w[32 + q] + x2 * m2_w[64 + q] + m2_b[q], 0.f);
                dotv += pj * psi_w[32 + q];
            }
            s->DNK[u] = dotv;
            float c0 = s->CX[p * 4 + 0], c1 = s->CX[p * 4 + 1], c2 = s->CX[p * 4 + 2];
            float dx = c0 - x0, dy = c1 - x1, dz = c2 - x2;
            float dist = sqrtf(dx * dx + dy * dy + dz * dz);
            s->MK[u] = ((c2 == x2) && (dist > 0.04f)) ? 1.f : 0.f;
        } else if (t < 194) {
            // center half of psi dot
            int p = t - 192;
            float c0 = s->CX[p * 4 + 0], c1 = s->CX[p * 4 + 1], c2 = s->CX[p * 4 + 2];
            float si = 0.f;
            #pragma unroll
            for (int q = 0; q < PDIM; ++q) {
                float pi = fmaxf(c0 * m1_w[q] + c1 * m1_w[32 + q] + c2 * m1_w[64 + q] + m1_b[q], 0.f);
                si += pi * psi_w[q];
            }
            s->SI[p] = si;
        }
        __syncthreads();

        // ---- Main GEMM: 64 rows (2 points x 32 nbrs) x 128 cols, K=128 ----
        // Thread: rows (row, row+32), 16 cols (8 packed f32x2 accumulators each).
        const float* xa = s->X + row * 132;
        const float* xb = s->X + (row + 32) * 132;
        unsigned long long accA[8], accB[8];
        #pragma unroll
        for (int i = 0; i < 8; ++i) { accA[i] = 0ull; accB[i] = 0ull; }

        #pragma unroll 4
        for (int c = 0; c < 128; ++c) {
            unsigned long long xa2 = pack2(xa[c]);
            unsigned long long xb2 = pack2(xb[c]);
            const ulonglong2* wr = W2 + c * 32 + cg;
            #pragma unroll
            for (int j = 0; j < 4; ++j) {
                ulonglong2 wv = wr[j * 8];
                accA[2 * j]     = fma2(xa2, wv.x, accA[2 * j]);
                accA[2 * j + 1] = fma2(xa2, wv.y, accA[2 * j + 1]);
                accB[2 * j]     = fma2(xb2, wv.x, accB[2 * j]);
                accB[2 * j + 1] = fma2(xb2, wv.y, accB[2 * j + 1]);
            }
        }

        // ---- r_f = dot(relu(theta_out + tb), feat_i) per (point,k) ----
        #pragma unroll
        for (int p = 0; p < 2; ++p) {
            unsigned long long* acc = p ? accB : accA;
            float part = 0.f;
            if (cg < 4) {
                #pragma unroll
                for (int j = 0; j < 4; ++j) {
                    float2 v0 = unpack2(acc[2 * j]);
                    float2 v1 = unpack2(acc[2 * j + 1]);
                    int o = cg * 16 + j * 4;
                    part += fmaxf(v0.x + s->TB[o],     0.f) * s->FI[p * 64 + o];
                    part += fmaxf(v0.y + s->TB[o + 1], 0.f) * s->FI[p * 64 + o + 1];
                    part += fmaxf(v1.x + s->TB[o + 2], 0.f) * s->FI[p * 64 + o + 2];
                    part += fmaxf(v1.y + s->TB[o + 3], 0.f) * s->FI[p * 64 + o + 3];
                }
            }
            part += __shfl_xor_sync(0xFFFFFFFFu, part, 1);
            part += __shfl_xor_sync(0xFFFFFFFFu, part, 2);
            if (cg == 0) s->RF[p * 32 + row] = part;
        }
        __syncthreads();

        // ---- masked, r_l-weighted softmax over K (warp 0 -> p0, warp 1 -> p1) ----
        if (w < 2) {
            int p = w, k = l;
            float rf = s->RF[p * 32 + k] * 0.125f;  // / sqrt(64)
            float m = rf;
            #pragma unroll
            for (int off = 16; off; off >>= 1)
                m = fmaxf(m, __shfl_xor_sync(0xFFFFFFFFu, m, off));
            float rl = fmaxf(s->SI[p] + s->DNK[p * 32 + k] + psib, 0.f)
                     * (1.f - s->MK[p * 32 + k]);
            float num = rl * expf(rf - m);
            float den = num;
            #pragma unroll
            for (int off = 16; off; off >>= 1)
                den += __shfl_xor_sync(0xFFFFFFFFu, den, off);
            den += 1e-8f;
            float Wk = num / den;
            s->Wk[p * 32 + k] = Wk;
            float sw = Wk;
            #pragma unroll
            for (int off = 16; off; off >>= 1)
                sw += __shfl_xor_sync(0xFFFFFFFFu, sw, off);
            if (k == 0) s->SumW[p] = sw;
        }
        __syncthreads();

        // ---- weighted reduction of z half over k ----
        #pragma unroll
        for (int p = 0; p < 2; ++p) {
            unsigned long long* acc = p ? accB : accA;
            float Wk = s->Wk[p * 32 + row];
            float v[16];
            #pragma unroll
            for (int j = 0; j < 4; ++j) {
                float2 v0 = unpack2(acc[2 * j]);
                float2 v1 = unpack2(acc[2 * j + 1]);
                v[j * 4 + 0] = v0.x * Wk;
                v[j * 4 + 1] = v0.y * Wk;
                v[j * 4 + 2] = v1.x * Wk;
                v[j * 4 + 3] = v1.y * Wk;
            }
            #pragma unroll
            for (int i = 0; i < 16; ++i) {
                v[i] += __shfl_xor_sync(0xFFFFFFFFu, v[i], 8);
                v[i] += __shfl_xor_sync(0xFFFFFFFFu, v[i], 16);
            }
            if (cg >= 4 && rloc == 0) {
                float* dst = s->Part + (p * 8 + w) * 64 + (cg - 4) * 16;
                #pragma unroll
                for (int i = 0; i < 16; ++i) dst[i] = v[i];
            }
        }
        __syncthreads();

        // ---- combine warp partials + z_b * sum(W), store ----
        if (t < 128) {
            int p = t >> 6, h = t & 63;
            float o = s->ZB[h] * s->SumW[p];
            #pragma unroll
            for (int w8 = 0; w8 < 8; ++w8)
                o += s->Part[(p * 8 + w8) * 64 + h];
            out[(size_t)(p0 + p) * HDIM + h] = o;
        }
        __syncthreads();
    }
}

extern "C" void kernel_launch(void* const* d_in, const int* in_sizes, int n_in,
                              void* d_out, int out_size) {
    const float* cxyz    = (const float*)d_in[0];
    const float* cfeat   = (const float*)d_in[1];
    const float* nxyz    = (const float*)d_in[2];
    const float* nfeat   = (const float*)d_in[3];
    const float* phi_w   = (const float*)d_in[4];
    const float* phi_b   = (const float*)d_in[5];
    const float* theta_w = (const float*)d_in[6];
    const float* theta_b = (const float*)d_in[7];
    const float* m1_w    = (const float*)d_in[8];
    const float* m1_b    = (const float*)d_in[9];
    const float* m2_w    = (const float*)d_in[10];
    const float* m2_b    = (const float*)d_in[11];
    const float* psi_w   = (const float*)d_in[12];
    const float* psi_b   = (const float*)d_in[13];
    const float* z_w     = (const float*)d_in[14];
    const float* z_b     = (const float*)d_in[15];
    float* out = (float*)d_out;

    cudaFuncSetAttribute(spil_kernel, cudaFuncAttributeMaxDynamicSharedMemorySize,
                         (int)sizeof(Smem));
    spil_kernel<<<NPTS / PPC, NTHR, sizeof(Smem)>>>(
        cxyz, cfeat, nxyz, nfeat, phi_w, phi_b, theta_w, theta_b,
        m1_w, m1_b, m2_w, m2_b, psi_w, psi_b, z_w, z_b, out);
}

// round 13
// speedup vs baseline: 2.1840x; 2.1793x over previous
#include <cuda_runtime.h>
#include <cuda_bf16.h>
#include <cstdint>

#define NTILES 8192     // 32768 points / 4 points per tile
#define NTHR   256
#define GRIDSZ 148

// ---- shared memory byte offsets ----
#define SM_XHI   0        // X hi bf16, 128x128, SW128 blocked atoms (32KB)
#define SM_XLO   32768
#define SM_WHI   65536    // [theta|z] weights hi (32KB)
#define SM_WLO   98304
#define SM_PHI   131072   // phi_w staged fp32 (32KB)
#define SM_CF    163840   // center features 4x128 (2KB)
#define SM_FI    165888   // feat_i 4x64 (1KB)
#define SM_TB    166912
#define SM_ZB    167168
#define SM_PB    167424
#define SM_DNK   167680   // 4x32
#define SM_MK    168192
#define SM_SI    168704   // 4
#define SM_WKS   168720   // 4x32
#define SM_SUMW  169232   // 4
#define SM_RF    169248   // 4x32
#define SM_NX    169760   // 4x32x3
#define SM_CX    171296   // 12
#define SMEM_BYTES 171392

__device__ __forceinline__ uint32_t s2u(const void* p) {
    uint32_t a;
    asm("{ .reg .u64 t; cvta.to.shared.u64 t, %1; cvt.u32.u64 %0, t; }" : "=r"(a) : "l"(p));
    return a;
}
// byte offset of (row r, bf16 col c) in a 128x128 bf16 tile stored as
// blocked SW128 atoms: atom = 8 rows x 64 cols (1024B), 16 atom-rows x 2 atom-cols.
__device__ __forceinline__ uint32_t swz(int r, int c) {
    uint32_t b = ((uint32_t)((r >> 3) + ((c >> 6) << 4)) << 10) + ((uint32_t)(r & 7) << 7)
               + ((uint32_t)(c & 63) << 1);
    return b ^ ((b >> 3) & 0x70);
}
__device__ __forceinline__ uint32_t swaddr(uint32_t base, int r, int c) {
    return base + swz(r, c);
}

#define LDSM4(r, a) \
    asm volatile("ldmatrix.sync.aligned.m8n8.x4.shared.b16 {%0,%1,%2,%3}, [%4];" \
        : "=r"((r)[0]), "=r"((r)[1]), "=r"((r)[2]), "=r"((r)[3]) : "r"(a))

#define MMA(d, a, b0, b1) \
    asm volatile("mma.sync.aligned.m16n8k16.row.col.f32.bf16.bf16.f32 " \
        "{%0,%1,%2,%3}, {%4,%5,%6,%7}, {%8,%9}, {%0,%1,%2,%3};" \
        : "+f"((d)[0]), "+f"((d)[1]), "+f"((d)[2]), "+f"((d)[3]) \
        : "r"((a)[0]), "r"((a)[1]), "r"((a)[2]), "r"((a)[3]), "r"(b0), "r"(b1))

__device__ __forceinline__ uint32_t pk(__nv_bfloat16 a, __nv_bfloat16 b) {
    __nv_bfloat162 v(a, b);
    return *reinterpret_cast<uint32_t*>(&v);
}

__global__ __launch_bounds__(NTHR, 1)
void spil_mma(const float* __restrict__ cxyz,  const float* __restrict__ cfeat,
              const float* __restrict__ nxyz,  const float* __restrict__ nfeat,
              const float* __restrict__ phi_w, const float* __restrict__ phi_b,
              const float* __restrict__ theta_w, const float* __restrict__ theta_b,
              const float* __restrict__ m1_w,  const float* __restrict__ m1_b,
              const float* __restrict__ m2_w,  const float* __restrict__ m2_b,
              const float* __restrict__ psi_w, const float* __restrict__ psi_b,
              const float* __restrict__ z_w,   const float* __restrict__ z_b,
              float* __restrict__ out)
{
    extern __shared__ char sm[];
    const uint32_t sb = s2u(sm);
    const int t = threadIdx.x;
    const int w = t >> 5;
    const int l = t & 31;

    float* PHIs  = (float*)(sm + SM_PHI);
    float* CFs   = (float*)(sm + SM_CF);
    float* FIs   = (float*)(sm + SM_FI);
    float* TBs   = (float*)(sm + SM_TB);
    float* ZBs   = (float*)(sm + SM_ZB);
    float* PBs   = (float*)(sm + SM_PB);
    float* DNKs  = (float*)(sm + SM_DNK);
    float* MKs   = (float*)(sm + SM_MK);
    float* SIs   = (float*)(sm + SM_SI);
    float* WKs   = (float*)(sm + SM_WKS);
    float* SUMWs = (float*)(sm + SM_SUMW);
    float* RFs   = (float*)(sm + SM_RF);
    float* NXs   = (float*)(sm + SM_NX);
    float* CXs   = (float*)(sm + SM_CX);

    // ---- once per CTA: weights [theta|z] -> bf16 hi/lo (swizzled), phi, biases
    for (int idx = t; idx < 16384; idx += NTHR) {
        int n = idx & 127, c = idx >> 7;
        float v = (n < 64) ? theta_w[c * 64 + n] : z_w[c * 64 + (n - 64)];
        __nv_bfloat16 h = __float2bfloat16(v);
        __nv_bfloat16 lo = __float2bfloat16(v - __bfloat162float(h));
        uint32_t a = swz(n, c);
        *(__nv_bfloat16*)(sm + SM_WHI + a) = h;
        *(__nv_bfloat16*)(sm + SM_WLO + a) = lo;
    }
    for (int idx = t; idx < 8192; idx += NTHR) PHIs[idx] = phi_w[idx];
    if (t < 64) { TBs[t] = theta_b[t]; ZBs[t] = z_b[t]; PBs[t] = phi_b[t]; }
    const float psib = psi_b[0];
    __syncthreads();

    // per-thread ldmatrix lane geometry
    const int mw = (w & 3) * 32;               // warp's M rows (point = w&3)
    const int nw = (w >> 2) * 64;              // warp's N cols (0: theta, 64: z)
    const int rA = mw + (l & 15);              // A lane row (tile0; tile1 +16)
    const int cA = (l >> 4) << 3;              // A lane k offset (0 or 8)
    const int rB = nw + ((l >> 4) << 3) + (l & 7);  // B lane row (n16 group 0)
    const int cB = ((l >> 3) & 1) << 3;        // B lane k offset

    const uint32_t xh = sb + SM_XHI, xl = sb + SM_XLO;
    const uint32_t wh = sb + SM_WHI, wl = sb + SM_WLO;

    for (int tile = blockIdx.x; tile < NTILES; tile += GRIDSZ) {
        const int pt = tile * 4;   // 4 points; GEMM row r = p*32 + k

        // ---- stage X: fp32 LDG -> bf16 hi/lo, swizzled STS ----
        {
            const float4* src = (const float4*)(nfeat + (size_t)pt * 4096);
            #pragma unroll 4
            for (int i = t; i < 4096; i += NTHR) {
                float4 v = src[i];
                int r = i >> 5, c = (i & 31) * 4;
                __nv_bfloat16 h0 = __float2bfloat16(v.x), h1 = __float2bfloat16(v.y);
                __nv_bfloat16 h2 = __float2bfloat16(v.z), h3 = __float2bfloat16(v.w);
                __nv_bfloat16 q0 = __float2bfloat16(v.x - __bfloat162float(h0));
                __nv_bfloat16 q1 = __float2bfloat16(v.y - __bfloat162float(h1));
                __nv_bfloat16 q2 = __float2bfloat16(v.z - __bfloat162float(h2));
                __nv_bfloat16 q3 = __float2bfloat16(v.w - __bfloat162float(h3));
                uint32_t a = swz(r, c);
                *(uint2*)(sm + SM_XHI + a) = make_uint2(pk(h0, h1), pk(h2, h3));
                *(uint2*)(sm + SM_XLO + a) = make_uint2(pk(q0, q1), pk(q2, q3));
            }
            CFs[t] = cfeat[(size_t)pt * 128 + t];
            CFs[256 + t] = cfeat[(size_t)pt * 128 + 256 + t];
            NXs[t] = nxyz[(size_t)pt * 96 + t];
            if (t < 128) NXs[256 + t] = nxyz[(size_t)pt * 96 + 256 + t];
            if (t < 12) CXs[t] = cxyz[(size_t)pt * 3 + t];
        }
        __syncthreads();

        // ---- side computations ----
        {   // feat_i = relu(cf @ phi + pb): 4 points x 64
            int p = t >> 6, h = t & 63;
            const float* cf = CFs + p * 128;
            const float* ph = PHIs + h;
            float a0 = 0.f, a1 = 0.f, a2 = 0.f, a3 = 0.f;
            #pragma unroll 8
            for (int c = 0; c < 128; c += 4) {
                a0 += cf[c]     * ph[c * 64];
                a1 += cf[c + 1] * ph[(c + 1) * 64];
                a2 += cf[c + 2] * ph[(c + 2) * 64];
                a3 += cf[c + 3] * ph[(c + 3) * 64];
            }
            FIs[t] = fmaxf(a0 + a1 + a2 + a3 + PBs[h], 0.f);
        }
        if (t < 128) {  // per (p,k): neighbor psi-dot + SPIL mask
            int p = t >> 5;
            const float* nx = NXs + t * 3;
            float x0 = nx[0], x1 = nx[1], x2 = nx[2];
            float dv = 0.f;
            #pragma unroll
            for (int q = 0; q < 32; ++q) {
                float pj = fmaxf(x0 * m2_w[q] + x1 * m2_w[32 + q] + x2 * m2_w[64 + q] + m2_b[q], 0.f);
                dv += pj * psi_w[32 + q];
            }
            DNKs[t] = dv;
            float c0 = CXs[p * 3], c1 = CXs[p * 3 + 1], c2 = CXs[p * 3 + 2];
            float dx = c0 - x0, dy = c1 - x1, dz = c2 - x2;
            float dist = sqrtf(dx * dx + dy * dy + dz * dz);
            MKs[t] = ((c2 == x2) && (dist > 0.04f)) ? 1.f : 0.f;
        } else if (t < 132) {  // center psi-dot per point
            int p = t - 128;
            float c0 = CXs[p * 3], c1 = CXs[p * 3 + 1], c2 = CXs[p * 3 + 2];
            float si = 0.f;
            #pragma unroll
            for (int q = 0; q < 32; ++q) {
                float pi = fmaxf(c0 * m1_w[q] + c1 * m1_w[32 + q] + c2 * m1_w[64 + q] + m1_b[q], 0.f);
                si += pi * psi_w[q];
            }
            SIs[p] = si;
        }
        __syncthreads();

        // ---- GEMM: warp (mw x 32, nw x 64), 3-split bf16 mma.sync ----
        float acc[2][8][4];
        #pragma unroll
        for (int i = 0; i < 2; ++i)
            #pragma unroll
            for (int j = 0; j < 8; ++j)
                #pragma unroll
                for (int q = 0; q < 4; ++q) acc[i][j][q] = 0.f;

        #pragma unroll
        for (int ks = 0; ks < 8; ++ks) {
            const int k0 = ks * 16;
            uint32_t a0[4], a1[4], e0[4], e1[4];
            LDSM4(a0, swaddr(xh, rA,      k0 + cA));
            LDSM4(a1, swaddr(xh, rA + 16, k0 + cA));
            LDSM4(e0, swaddr(xl, rA,      k0 + cA));
            LDSM4(e1, swaddr(xl, rA + 16, k0 + cA));
            #pragma unroll
            for (int g = 0; g < 4; ++g) {
                uint32_t bh[4], bl[4];
                LDSM4(bh, swaddr(wh, rB + 16 * g, k0 + cB));
                LDSM4(bl, swaddr(wl, rB + 16 * g, k0 + cB));
                // hi*hi
                MMA(acc[0][2 * g],     a0, bh[0], bh[1]);
                MMA(acc[0][2 * g + 1], a0, bh[2], bh[3]);
                MMA(acc[1][2 * g],     a1, bh[0], bh[1]);
                MMA(acc[1][2 * g + 1], a1, bh[2], bh[3]);
                // hi*lo
                MMA(acc[0][2 * g],     a0, bl[0], bl[1]);
                MMA(acc[0][2 * g + 1], a0, bl[2], bl[3]);
                MMA(acc[1][2 * g],     a1, bl[0], bl[1]);
                MMA(acc[1][2 * g + 1], a1, bl[2], bl[3]);
                // lo*hi
                MMA(acc[0][2 * g],     e0, bh[0], bh[1]);
                MMA(acc[0][2 * g + 1], e0, bh[2], bh[3]);
                MMA(acc[1][2 * g],     e1, bh[0], bh[1]);
                MMA(acc[1][2 * g + 1], e1, bh[2], bh[3]);
            }
        }

        // Fragment layout: acc[tile][n8][half*2+j] holds
        //   row = mw + tile*16 + half*8 + (l>>2),  col = nw + n8*8 + 2*(l&3) + j

        // ---- theta warps (w<4): r_f + masked r_l-weighted softmax ----
        if (w < 4) {
            const int p = w;
            float part[4];
            #pragma unroll
            for (int th = 0; th < 4; ++th) {
                const int ti = th >> 1, hf = th & 1;
                float s = 0.f;
                #pragma unroll
                for (int n8 = 0; n8 < 8; ++n8) {
                    int col = n8 * 8 + 2 * (l & 3);
                    s += fmaxf(acc[ti][n8][hf * 2 + 0] + TBs[col],     0.f) * FIs[p * 64 + col];
                    s += fmaxf(acc[ti][n8][hf * 2 + 1] + TBs[col + 1], 0.f) * FIs[p * 64 + col + 1];
                }
                s += __shfl_xor_sync(0xFFFFFFFFu, s, 1);
                s += __shfl_xor_sync(0xFFFFFFFFu, s, 2);
                part[th] = s;
            }
            if ((l & 3) == 0) {
                #pragma unroll
                for (int th = 0; th < 4; ++th)
                    RFs[p * 32 + (th >> 1) * 16 + (th & 1) * 8 + (l >> 2)] = part[th];
            }
            __syncwarp();
            // softmax: lane = k
            float rf = RFs[p * 32 + l] * 0.125f;   // / sqrt(64)
            float m = rf;
            #pragma unroll
            for (int off = 16; off; off >>= 1)
                m = fmaxf(m, __shfl_xor_sync(0xFFFFFFFFu, m, off));
            float rl = fmaxf(SIs[p] + DNKs[p * 32 + l] + psib, 0.f) * (1.f - MKs[p * 32 + l]);
            float num = rl * expf(rf - m);
            float den = num;
            #pragma unroll
            for (int off = 16; off; off >>= 1)
                den += __shfl_xor_sync(0xFFFFFFFFu, den, off);
            den += 1e-8f;
            float Wk = num / den;
            WKs[p * 32 + l] = Wk;
            float sw_ = Wk;
            #pragma unroll
            for (int off = 16; off; off >>= 1)
                sw_ += __shfl_xor_sync(0xFFFFFFFFu, sw_, off);
            if (l == 0) SUMWs[p] = sw_;
        }
        __syncthreads();

        // ---- z warps (w>=4): Wk-weighted reduction over k, direct store ----
        if (w >= 4) {
            const int p = w - 4;
            float wk[4];
            #pragma unroll
            for (int th = 0; th < 4; ++th)
                wk[th] = WKs[p * 32 + (th >> 1) * 16 + (th & 1) * 8 + (l >> 2)];
            const float swp = SUMWs[p];
            #pragma unroll
            for (int n8 = 0; n8 < 8; ++n8) {
                #pragma unroll
                for (int j = 0; j < 2; ++j) {
                    float s = wk[0] * acc[0][n8][j]     + wk[1] * acc[0][n8][2 + j]
                            + wk[2] * acc[1][n8][j]     + wk[3] * acc[1][n8][2 + j];
                    s += __shfl_xor_sync(0xFFFFFFFFu, s, 4);
                    s += __shfl_xor_sync(0xFFFFFFFFu, s, 8);
                    s += __shfl_xor_sync(0xFFFFFFFFu, s, 16);
                    if (l < 4) {
                        int h = n8 * 8 + 2 * l + j;
                        out[(size_t)(pt + p) * 64 + h] = s + ZBs[h] * swp;
                    }
                }
            }
        }
        __syncthreads();
    }
}

extern "C" void kernel_launch(void* const* d_in, const int* in_sizes, int n_in,
                              void* d_out, int out_size) {
    const float* cxyz    = (const float*)d_in[0];
    const float* cfeat   = (const float*)d_in[1];
    const float* nxyz    = (const float*)d_in[2];
    const float* nfeat   = (const float*)d_in[3];
    const float* phi_w   = (const float*)d_in[4];
    const float* phi_b   = (const float*)d_in[5];
    const float* theta_w = (const float*)d_in[6];
    const float* theta_b = (const float*)d_in[7];
    const float* m1_w    = (const float*)d_in[8];
    const float* m1_b    = (const float*)d_in[9];
    const float* m2_w    = (const float*)d_in[10];
    const float* m2_b    = (const float*)d_in[11];
    const float* psi_w   = (const float*)d_in[12];
    const float* psi_b   = (const float*)d_in[13];
    const float* z_w     = (const float*)d_in[14];
    const float* z_b     = (const float*)d_in[15];
    float* out = (float*)d_out;

    cudaFuncSetAttribute(spil_mma, cudaFuncAttributeMaxDynamicSharedMemorySize, SMEM_BYTES);
    spil_mma<<<GRIDSZ, NTHR, SMEM_BYTES>>>(
        cxyz, cfeat, nxyz, nfeat, phi_w, phi_b, theta_w, theta_b,
        m1_w, m1_b, m2_w, m2_b, psi_w, psi_b, z_w, z_b, out);
}

// round 14
// speedup vs baseline: 2.8662x; 1.3124x over previous
#include <cuda_runtime.h>
#include <cuda_bf16.h>
#include <cstdint>

#define NTILES 16384    // 32768 points / 2 points per tile
#define NTHR   256
#define GRIDSZ 296      // 2 CTAs per SM x 148

// ---- shared memory byte offsets (per CTA, ~100KB total) ----
#define SM_XHI   0        // X hi bf16, 64x128, SW128 blocked atoms (16KB)
#define SM_XLO   16384
#define SM_WHI   32768    // [theta|z] weights hi, 128x128 (32KB)
#define SM_WLO   65536
#define SM_CF    98304    // center features 2x128 (1KB)
#define SM_FI    99328    // feat_i 2x64 (512B)
#define SM_TB    99840    // theta_b (256B)
#define SM_ZB    100096   // z_b
#define SM_DNK   100352   // 2x32
#define SM_MK    100608   // 2x32
#define SM_SI    100864   // 2 (+pad)
#define SM_WKS   100880   // 2x32
#define SM_SUMW  101136   // 2 (+pad)
#define SM_RFP   101152   // r_f partials: 2(wn) x 2(p) x 32(k) = 512B
#define SM_NX    101664   // 2x32x3 (768B)
#define SM_CX    102432   // 6 (+pad)
#define SMEM_BYTES 102464

__device__ __forceinline__ uint32_t s2u(const void* p) {
    uint32_t a;
    asm("{ .reg .u64 t; cvta.to.shared.u64 t, %1; cvt.u32.u64 %0, t; }" : "=r"(a) : "l"(p));
    return a;
}
// X tile: 64 rows x 128 bf16 cols, blocked SW128 atoms (8 atom-rows x 2 atom-cols)
__device__ __forceinline__ uint32_t swzX(int r, int c) {
    uint32_t b = ((uint32_t)((r >> 3) + ((c >> 6) << 3)) << 10) + ((uint32_t)(r & 7) << 7)
               + ((uint32_t)(c & 63) << 1);
    return b ^ ((b >> 3) & 0x70);
}
// W tile: 128 rows x 128 bf16 cols (16 atom-rows x 2 atom-cols)
__device__ __forceinline__ uint32_t swzW(int r, int c) {
    uint32_t b = ((uint32_t)((r >> 3) + ((c >> 6) << 4)) << 10) + ((uint32_t)(r & 7) << 7)
               + ((uint32_t)(c & 63) << 1);
    return b ^ ((b >> 3) & 0x70);
}

#define LDSM4(r, a) \
    asm volatile("ldmatrix.sync.aligned.m8n8.x4.shared.b16 {%0,%1,%2,%3}, [%4];" \
        : "=r"((r)[0]), "=r"((r)[1]), "=r"((r)[2]), "=r"((r)[3]) : "r"(a))

#define MMA(d, a, b0, b1) \
    asm volatile("mma.sync.aligned.m16n8k16.row.col.f32.bf16.bf16.f32 " \
        "{%0,%1,%2,%3}, {%4,%5,%6,%7}, {%8,%9}, {%0,%1,%2,%3};" \
        : "+f"((d)[0]), "+f"((d)[1]), "+f"((d)[2]), "+f"((d)[3]) \
        : "r"((a)[0]), "r"((a)[1]), "r"((a)[2]), "r"((a)[3]), "r"(b0), "r"(b1))

// Truncation-based hi/lo split of two fp32 values.
// hi bf16 = top 16 bits (PRMT pack); lo = v - hi is EXACT, then rn-rounded to bf16.
// Dropped lo*lo term in the 3-product GEMM is ~2^-16 relative.
__device__ __forceinline__ void split2(float x, float y, uint32_t& hi, uint32_t& lo) {
    uint32_t bx = __float_as_uint(x), by = __float_as_uint(y);
    hi = __byte_perm(bx, by, 0x7632);
    float lx = x - __uint_as_float(bx & 0xFFFF0000u);
    float ly = y - __uint_as_float(by & 0xFFFF0000u);
    asm("cvt.rn.bf16x2.f32 %0, %1, %2;" : "=r"(lo) : "f"(ly), "f"(lx));
}

__global__ __launch_bounds__(NTHR, 2)
void spil_mma2(const float* __restrict__ cxyz,  const float* __restrict__ cfeat,
               const float* __restrict__ nxyz,  const float* __restrict__ nfeat,
               const float* __restrict__ phi_w, const float* __restrict__ phi_b,
               const float* __restrict__ theta_w, const float* __restrict__ theta_b,
               const float* __restrict__ m1_w,  const float* __restrict__ m1_b,
               const float* __restrict__ m2_w,  const float* __restrict__ m2_b,
               const float* __restrict__ psi_w, const float* __restrict__ psi_b,
               const float* __restrict__ z_w,   const float* __restrict__ z_b,
               float* __restrict__ out)
{
    extern __shared__ char sm[];
    const uint32_t sb = s2u(sm);
    const int t = threadIdx.x;
    const int w = t >> 5;
    const int l = t & 31;

    float* CFs   = (float*)(sm + SM_CF);
    float* FIs   = (float*)(sm + SM_FI);
    float* TBs   = (float*)(sm + SM_TB);
    float* ZBs   = (float*)(sm + SM_ZB);
    float* DNKs  = (float*)(sm + SM_DNK);
    float* MKs   = (float*)(sm + SM_MK);
    float* SIs   = (float*)(sm + SM_SI);
    float* WKs   = (float*)(sm + SM_WKS);
    float* SUMWs = (float*)(sm + SM_SUMW);
    float* RFp   = (float*)(sm + SM_RFP);
    float* NXs   = (float*)(sm + SM_NX);
    float* CXs   = (float*)(sm + SM_CX);

    // ---- once per CTA: weights [theta|z] -> bf16 hi/lo (swizzled), biases ----
    for (int idx = t; idx < 8192; idx += NTHR) {
        int n = idx & 127, cc = (idx >> 7) * 2;   // column pair (cc, cc+1)
        float v0 = (n < 64) ? theta_w[cc * 64 + n]       : z_w[cc * 64 + (n - 64)];
        float v1 = (n < 64) ? theta_w[(cc + 1) * 64 + n] : z_w[(cc + 1) * 64 + (n - 64)];
        uint32_t h, lo;
        split2(v0, v1, h, lo);
        uint32_t a = swzW(n, cc);
        *(uint32_t*)(sm + SM_WHI + a) = h;
        *(uint32_t*)(sm + SM_WLO + a) = lo;
    }
    if (t < 64) { TBs[t] = theta_b[t]; ZBs[t] = z_b[t]; }
    const float psib = psi_b[0];
    __syncthreads();

    // warp geometry: p = point (m-half), wn = 32-col n-block (0,1: theta; 2,3: z)
    const int p  = w & 1;
    const int wn = w >> 1;
    const int rA = p * 32 + (l & 15);
    const int cA = (l >> 4) << 3;
    const int rB = wn * 32 + ((l >> 4) << 3) + (l & 7);
    const int cB = ((l >> 3) & 1) << 3;

    const uint32_t xh = sb + SM_XHI, xl = sb + SM_XLO;
    const uint32_t wh = sb + SM_WHI, wl = sb + SM_WLO;

    for (int tile = blockIdx.x; tile < NTILES; tile += GRIDSZ) {
        const int pt = tile * 2;   // 2 points; GEMM row r = p*32 + k

        // ---- stage X: fp32 LDG -> bf16 hi/lo (cheap split), swizzled STS ----
        {
            const float4* src = (const float4*)(nfeat + (size_t)pt * 4096);
            #pragma unroll
            for (int j = 0; j < 8; ++j) {
                int i = t + NTHR * j;           // 2048 float4 total
                float4 v = src[i];
                int r = i >> 5, c = (i & 31) * 4;
                uint32_t h01, l01, h23, l23;
                split2(v.x, v.y, h01, l01);
                split2(v.z, v.w, h23, l23);
                uint32_t a = swzX(r, c);
                *(uint2*)(sm + SM_XHI + a) = make_uint2(h01, h23);
                *(uint2*)(sm + SM_XLO + a) = make_uint2(l01, l23);
            }
            CFs[t] = cfeat[(size_t)pt * 128 + t];          // 2x128
            if (t < 192) NXs[t] = nxyz[(size_t)pt * 96 + t];
            if (t < 6)   CXs[t] = cxyz[(size_t)pt * 3 + t];
        }
        __syncthreads();

        // ---- side computations (overlapped by the other CTA's GEMM) ----
        if (t < 128) {  // feat_i = relu(cf @ phi + pb): 2 points x 64
            int pp = t >> 6, h = t & 63;
            const float* cf = CFs + pp * 128;
            const float* ph = phi_w + h;
            float a0 = 0.f, a1 = 0.f, a2 = 0.f, a3 = 0.f;
            #pragma unroll 8
            for (int c = 0; c < 128; c += 4) {
                a0 += cf[c]     * __ldg(ph + c * 64);
                a1 += cf[c + 1] * __ldg(ph + (c + 1) * 64);
                a2 += cf[c + 2] * __ldg(ph + (c + 2) * 64);
                a3 += cf[c + 3] * __ldg(ph + (c + 3) * 64);
            }
            FIs[t] = fmaxf(a0 + a1 + a2 + a3 + __ldg(phi_b + h), 0.f);
        } else if (t < 192) {  // per (p,k): neighbor psi-dot + SPIL mask
            int u = t - 128, pp = u >> 5;
            const float* nx = NXs + u * 3;
            float x0 = nx[0], x1 = nx[1], x2 = nx[2];
            float dv = 0.f;
            #pragma unroll
            for (int q = 0; q < 32; ++q) {
                float pj = fmaxf(x0 * __ldg(m2_w + q) + x1 * __ldg(m2_w + 32 + q)
                               + x2 * __ldg(m2_w + 64 + q) + __ldg(m2_b + q), 0.f);
                dv += pj * __ldg(psi_w + 32 + q);
            }
            DNKs[u] = dv;
            float c0 = CXs[pp * 3], c1 = CXs[pp * 3 + 1], c2 = CXs[pp * 3 + 2];
            float dx = c0 - x0, dy = c1 - x1, dz = c2 - x2;
            float dist = sqrtf(dx * dx + dy * dy + dz * dz);
            MKs[u] = ((c2 == x2) && (dist > 0.04f)) ? 1.f : 0.f;
        } else if (t < 194) {  // center psi-dot per point
            int pp = t - 192;
            float c0 = CXs[pp * 3], c1 = CXs[pp * 3 + 1], c2 = CXs[pp * 3 + 2];
            float si = 0.f;
            #pragma unroll
            for (int q = 0; q < 32; ++q) {
                float pi = fmaxf(c0 * __ldg(m1_w + q) + c1 * __ldg(m1_w + 32 + q)
                               + c2 * __ldg(m1_w + 64 + q) + __ldg(m1_b + q), 0.f);
                si += pi * __ldg(psi_w + q);
            }
            SIs[pp] = si;
        }

        // ---- GEMM: warp (p*32 rows x wn*32 cols), 3-split bf16 mma.sync ----
        float acc[2][4][4];
        #pragma unroll
        for (int i = 0; i < 2; ++i)
            #pragma unroll
            for (int j = 0; j < 4; ++j)
                #pragma unroll
                for (int q = 0; q < 4; ++q) acc[i][j][q] = 0.f;

        #pragma unroll
        for (int ks = 0; ks < 8; ++ks) {
            const int k0 = ks * 16;
            uint32_t a0[4], a1[4], e0[4], e1[4];
            LDSM4(a0, xh + swzX(rA,      k0 + cA));
            LDSM4(a1, xh + swzX(rA + 16, k0 + cA));
            LDSM4(e0, xl + swzX(rA,      k0 + cA));
            LDSM4(e1, xl + swzX(rA + 16, k0 + cA));
            #pragma unroll
            for (int g = 0; g < 2; ++g) {
                uint32_t bh[4], bl[4];
                LDSM4(bh, wh + swzW(rB + 16 * g, k0 + cB));
                LDSM4(bl, wl + swzW(rB + 16 * g, k0 + cB));
                // hi*hi
                MMA(acc[0][2 * g],     a0, bh[0], bh[1]);
                MMA(acc[0][2 * g + 1], a0, bh[2], bh[3]);
                MMA(acc[1][2 * g],     a1, bh[0], bh[1]);
                MMA(acc[1][2 * g + 1], a1, bh[2], bh[3]);
                // hi*lo
                MMA(acc[0][2 * g],     a0, bl[0], bl[1]);
                MMA(acc[0][2 * g + 1], a0, bl[2], bl[3]);
                MMA(acc[1][2 * g],     a1, bl[0], bl[1]);
                MMA(acc[1][2 * g + 1], a1, bl[2], bl[3]);
                // lo*hi
                MMA(acc[0][2 * g],     e0, bh[0], bh[1]);
                MMA(acc[0][2 * g + 1], e0, bh[2], bh[3]);
                MMA(acc[1][2 * g],     e1, bh[0], bh[1]);
                MMA(acc[1][2 * g + 1], e1, bh[2], bh[3]);
            }
        }

        // Fragment: acc[ti][n8][hf*2+j] -> row = p*32 + ti*16 + hf*8 + (l>>2),
        //                                  col = wn*32 + n8*8 + 2*(l&3) + j

        // ---- theta warps (wn<2): r_f partial dot over this warp's 32 cols ----
        if (wn < 2) {
            float part[4];
            #pragma unroll
            for (int th = 0; th < 4; ++th) {
                const int ti = th >> 1, hf = th & 1;
                float s = 0.f;
                #pragma unroll
                for (int n8 = 0; n8 < 4; ++n8) {
                    int col = wn * 32 + n8 * 8 + 2 * (l & 3);
                    s += fmaxf(acc[ti][n8][hf * 2 + 0] + TBs[col],     0.f) * FIs[p * 64 + col];
                    s += fmaxf(acc[ti][n8][hf * 2 + 1] + TBs[col + 1], 0.f) * FIs[p * 64 + col + 1];
                }
                s += __shfl_xor_sync(0xFFFFFFFFu, s, 1);
                s += __shfl_xor_sync(0xFFFFFFFFu, s, 2);
                part[th] = s;
            }
            if ((l & 3) == 0) {
                #pragma unroll
                for (int th = 0; th < 4; ++th)
                    RFp[wn * 64 + p * 32 + (th >> 1) * 16 + (th & 1) * 8 + (l >> 2)] = part[th];
            }
        }
        __syncthreads();

        // ---- softmax (warp 0 -> point 0, warp 1 -> point 1), lane = k ----
        if (w < 2) {
            const int pp = w;
            float rf = (RFp[pp * 32 + l] + RFp[64 + pp * 32 + l]) * 0.125f;  // /sqrt(64)
            float m = rf;
            #pragma unroll
            for (int off = 16; off; off >>= 1)
                m = fmaxf(m, __shfl_xor_sync(0xFFFFFFFFu, m, off));
            float rl = fmaxf(SIs[pp] + DNKs[pp * 32 + l] + psib, 0.f) * (1.f - MKs[pp * 32 + l]);
            float num = rl * expf(rf - m);
            float den = num;
            #pragma unroll
            for (int off = 16; off; off >>= 1)
                den += __shfl_xor_sync(0xFFFFFFFFu, den, off);
            den += 1e-8f;
            float Wk = num / den;
            WKs[pp * 32 + l] = Wk;
            float sw_ = Wk;
            #pragma unroll
            for (int off = 16; off; off >>= 1)
                sw_ += __shfl_xor_sync(0xFFFFFFFFu, sw_, off);
            if (l == 0) SUMWs[pp] = sw_;
        }
        __syncthreads();

        // ---- z warps (wn>=2): Wk-weighted reduction over k, direct store ----
        if (wn >= 2) {
            float wk[4];
            #pragma unroll
            for (int th = 0; th < 4; ++th)
                wk[th] = WKs[p * 32 + (th >> 1) * 16 + (th & 1) * 8 + (l >> 2)];
            const float swp = SUMWs[p];
            #pragma unroll
            for (int n8 = 0; n8 < 4; ++n8) {
                #pragma unroll
                for (int j = 0; j < 2; ++j) {
                    float s = wk[0] * acc[0][n8][j] + wk[1] * acc[0][n8][2 + j]
                            + wk[2] * acc[1][n8][j] + wk[3] * acc[1][n8][2 + j];
                    s += __shfl_xor_sync(0xFFFFFFFFu, s, 4);
                    s += __shfl_xor_sync(0xFFFFFFFFu, s, 8);
                    s += __shfl_xor_sync(0xFFFFFFFFu, s, 16);
                    if (l < 4) {
                        int h = (wn - 2) * 32 + n8 * 8 + 2 * l + j;
                        out[(size_t)(pt + p) * 64 + h] = s + ZBs[h] * swp;
                    }
                }
            }
        }
        __syncthreads();
    }
}

extern "C" void kernel_launch(void* const* d_in, const int* in_sizes, int n_in,
                              void* d_out, int out_size) {
    const float* cxyz    = (const float*)d_in[0];
    const float* cfeat   = (const float*)d_in[1];
    const float* nxyz    = (const float*)d_in[2];
    const float* nfeat   = (const float*)d_in[3];
    const float* phi_w   = (const float*)d_in[4];
    const float* phi_b   = (const float*)d_in[5];
    const float* theta_w = (const float*)d_in[6];
    const float* theta_b = (const float*)d_in[7];
    const float* m1_w    = (const float*)d_in[8];
    const float* m1_b    = (const float*)d_in[9];
    const float* m2_w    = (const float*)d_in[10];
    const float* m2_b    = (const float*)d_in[11];
    const float* psi_w   = (const float*)d_in[12];
    const float* psi_b   = (const float*)d_in[13];
    const float* z_w     = (const float*)d_in[14];
    const float* z_b     = (const float*)d_in[15];
    float* out = (float*)d_out;

    cudaFuncSetAttribute(spil_mma2, cudaFuncAttributeMaxDynamicSharedMemorySize, SMEM_BYTES);
    spil_mma2<<<GRIDSZ, NTHR, SMEM_BYTES>>>(
        cxyz, cfeat, nxyz, nfeat, phi_w, phi_b, theta_w, theta_b,
        m1_w, m1_b, m2_w, m2_b, psi_w, psi_b, z_w, z_b, out);
}